// round 16
// baseline (speedup 1.0000x reference)
#include <cuda_runtime.h>
#include <cuda_fp16.h>
#include <math.h>

#define NN 50000
#define MM 50000
#define EE 1600000
#define DD 128
#define SW 136   // smem tile stride in halves (272B: ldmatrix-aligned, conflict-free)

// Scratch (allocation-free rule: __device__ globals)
__device__ __half g_qh[NN * DD];
__device__ __half g_k[MM * DD];
__device__ __half g_v[MM * DD];
__device__ float  g_p[EE];        // exp(score) per edge
__device__ int    g_rowptr[NN + 1];

__device__ __forceinline__ float gelu_fast(float x) {
    float u = x * fmaf(x * x, 0.0356774081f, 0.7978845608f);
    float th;
    asm("tanh.approx.f32 %0, %1;" : "=f"(th) : "f"(u));
    return 0.5f * x * (1.0f + th);
}

__device__ __forceinline__ void mma16816(float* c,
    unsigned a0, unsigned a1, unsigned a2, unsigned a3,
    unsigned b0, unsigned b1)
{
    asm volatile(
        "mma.sync.aligned.m16n8k16.row.col.f32.f16.f16.f32 "
        "{%0,%1,%2,%3}, {%4,%5,%6,%7}, {%8,%9}, {%0,%1,%2,%3};\n"
        : "+f"(c[0]), "+f"(c[1]), "+f"(c[2]), "+f"(c[3])
        : "r"(a0), "r"(a1), "r"(a2), "r"(a3), "r"(b0), "r"(b1));
}

// ---------------------------------------------------------------------------
// Tensor-core projection: Y = gelu(X @ W + b), fp16 HMMA, fp32 accum.
// (unchanged — measured stable; ldmatrix A/B, coalesced epilogue)
// ---------------------------------------------------------------------------
__global__ __launch_bounds__(256, 2) void proj_mma_kernel(
    const float* __restrict__ query, const float* __restrict__ memory,
    const float* __restrict__ Wq, const float* __restrict__ bq,
    const float* __restrict__ Wk, const float* __restrict__ bk,
    const float* __restrict__ Wv, const float* __restrict__ bv)
{
    extern __shared__ __half smem[];
    __half* sW = smem;             // 128 x SW halves
    __half* sX = smem + 128 * SW;  // 128 x SW halves (reused for output)

    const float* X; const float* W; const float* b; __half* Y;
    if (blockIdx.y == 0)      { X = query;  W = Wq; b = bq; Y = g_qh; }
    else if (blockIdx.y == 1) { X = memory; W = Wk; b = bk; Y = g_k; }
    else                      { X = memory; W = Wv; b = bv; Y = g_v; }
    const int R = NN;

    const int t = threadIdx.x;
    const int row_base = blockIdx.x * 128;

    {
        const float2* W2 = (const float2*)W;
        const float2* X2 = (const float2*)X;
        #pragma unroll
        for (int i = t; i < 8192; i += 256) {
            int row = i >> 6;
            int col = (i & 63) * 2;
            float2 wv = W2[i];
            *(__half2*)(sW + row * SW + col) = __floats2half2_rn(wv.x, wv.y);
            int xr = row_base + row;
            if (xr > R - 1) xr = R - 1;
            float2 xv = X2[(size_t)xr * 64 + (i & 63)];
            *(__half2*)(sX + row * SW + col) = __floats2half2_rn(xv.x, xv.y);
        }
    }
    __syncthreads();

    const int w = t >> 5;
    const int lane = t & 31;
    const int g = lane >> 2;
    const int tg = lane & 3;
    const int mloc = w * 16;

    float acc[16][4];
    #pragma unroll
    for (int i = 0; i < 16; i++) {
        acc[i][0] = 0.f; acc[i][1] = 0.f; acc[i][2] = 0.f; acc[i][3] = 0.f;
    }

    const int a_row = mloc + (lane & 15);
    const int a_koff = (lane >> 4) << 3;
    const int lrow = lane & 15;
    const int lcoff = (lane >> 4) << 3;

    #pragma unroll
    for (int ks = 0; ks < 8; ks++) {
        unsigned a0, a1, a2, a3;
        unsigned abase = (unsigned)__cvta_generic_to_shared(
            sX + a_row * SW + ks * 16 + a_koff);
        asm volatile(
            "ldmatrix.sync.aligned.m8n8.x4.shared.b16 {%0,%1,%2,%3}, [%4];\n"
            : "=r"(a0), "=r"(a1), "=r"(a2), "=r"(a3) : "r"(abase));

        unsigned bbase = (unsigned)__cvta_generic_to_shared(
            sW + (ks * 16 + lrow) * SW + lcoff);
        #pragma unroll
        for (int nt = 0; nt < 16; nt += 2) {
            unsigned b0, b1, b2, b3;
            asm volatile(
                "ldmatrix.sync.aligned.m8n8.x4.trans.shared.b16 "
                "{%0,%1,%2,%3}, [%4];\n"
                : "=r"(b0), "=r"(b1), "=r"(b2), "=r"(b3)
                : "r"(bbase + (unsigned)(nt * 8 * 2)));
            mma16816(acc[nt],     a0, a1, a2, a3, b0, b1);
            mma16816(acc[nt + 1], a0, a1, a2, a3, b2, b3);
        }
    }

    __syncthreads();
    #pragma unroll
    for (int nt = 0; nt < 16; nt++) {
        int col = nt * 8 + 2 * tg;
        float2 bias = *(const float2*)(b + col);
        float o0 = gelu_fast(acc[nt][0] + bias.x);
        float o1 = gelu_fast(acc[nt][1] + bias.y);
        float o2 = gelu_fast(acc[nt][2] + bias.x);
        float o3 = gelu_fast(acc[nt][3] + bias.y);
        *(__half2*)(sX + (mloc + g) * SW + col)     = __floats2half2_rn(o0, o1);
        *(__half2*)(sX + (mloc + 8 + g) * SW + col) = __floats2half2_rn(o2, o3);
    }
    __syncthreads();

    {
        const int lr = t >> 4;
        const int c16 = t & 15;
        #pragma unroll
        for (int it = 0; it < 8; it++) {
            int row_local = it * 16 + lr;
            int row = row_base + row_local;
            if (row < R) {
                uint4 val = *(const uint4*)(sX + row_local * SW + c16 * 8);
                *(uint4*)(Y + (size_t)row * DD + c16 * 8) = val;
            }
        }
    }
}

// ---------------------------------------------------------------------------
// CSR row pointers from sorted rows[] via lower_bound.
// ---------------------------------------------------------------------------
__global__ void build_rowptr(const int* __restrict__ rows) {
    int i = blockIdx.x * blockDim.x + threadIdx.x;
    if (i > NN) return;
    int lo = 0, hi = EE;
    while (lo < hi) {
        int mid = (lo + hi) >> 1;
        if (rows[mid] < i) lo = mid + 1; else hi = mid;
    }
    g_rowptr[i] = lo;
}

// ---------------------------------------------------------------------------
// Edge-parallel scores, wavefront-optimal gather shape:
// half-warp (16 lanes) per edge; each lane loads ONE uint4 (8 halves) of
// q and of k, so one LDG.128 covers 2 full 256B rows (4 lines -> 4
// wavefronts per 2 edges, vs 8/edge in the 4-lane layout).
// Dot: 4 HFMA2/lane (fp16 chain depth 4, same as before), fp32 reduce
// over 16 lanes (4 shfl). p = exp2(s * adj * scale * log2e) stored.
// No max subtraction: gelu-bounded scores make plain exp safe.
// ---------------------------------------------------------------------------
__global__ __launch_bounds__(256) void score_kernel(
    const int* __restrict__ rows, const int* __restrict__ cols,
    const float* __restrict__ adj)
{
    int gidx = blockIdx.x * 256 + threadIdx.x;
    int e = gidx >> 4;                // half-warp per edge
    if (e >= EE) return;
    int l16 = gidx & 15;              // lane within half-warp: 8 dims @ l16*8

    int r = rows[e];
    int c = cols[e];

    uint4 a = *(const uint4*)(g_qh + (size_t)r * DD + l16 * 8);
    uint4 b = *(const uint4*)(g_k  + (size_t)c * DD + l16 * 8);

    __half2 ac = __hmul2(*(__half2*)&a.x, *(__half2*)&b.x);
    ac = __hfma2(*(__half2*)&a.y, *(__half2*)&b.y, ac);
    ac = __hfma2(*(__half2*)&a.z, *(__half2*)&b.z, ac);
    ac = __hfma2(*(__half2*)&a.w, *(__half2*)&b.w, ac);
    float2 f = __half22float2(ac);
    float s = f.x + f.y;

    s += __shfl_xor_sync(0xFFFFFFFFu, s, 1);
    s += __shfl_xor_sync(0xFFFFFFFFu, s, 2);
    s += __shfl_xor_sync(0xFFFFFFFFu, s, 4);
    s += __shfl_xor_sync(0xFFFFFFFFu, s, 8);

    if (l16 == 0) {
        float m = adj[e] * 0.1275611217f;   // (1/sqrt(128)) * log2(e)
        g_p[e] = exp2f(s * m);
    }
}

// ---------------------------------------------------------------------------
// Warp-per-row, 2 edges per iteration (proven R12 shape):
// half-warp h handles edge e+h; its 16 lanes each load a uint4 (8 dims,
// LDG.128) of v -> 2 wavefronts/edge. Cross-half merge once per row.
// ---------------------------------------------------------------------------
__global__ __launch_bounds__(256) void attn_row_kernel(
    const int* __restrict__ cols, float* __restrict__ out)
{
    int row = (blockIdx.x * blockDim.x + threadIdx.x) >> 5;
    int lane = threadIdx.x & 31;
    if (row >= NN) return;

    int e0 = g_rowptr[row];
    int e1 = g_rowptr[row + 1];

    float* orow = out + (size_t)row * DD;
    const int half = lane >> 4;       // 0 or 1: which edge of the pair
    const int l16 = lane & 15;        // dim group: 8 dims starting at l16*8

    if (e0 == e1) {
        if (half == 0) {
            float4 z = {0.f, 0.f, 0.f, 0.f};
            ((float4*)orow)[l16 * 2]     = z;
            ((float4*)orow)[l16 * 2 + 1] = z;
        }
        return;
    }

    const int c_fallback = cols[e0];  // valid index for the padded edge

    float d = 0.f;
    float a0 = 0.f, a1 = 0.f, a2 = 0.f, a3 = 0.f;
    float a4 = 0.f, a5 = 0.f, a6 = 0.f, a7 = 0.f;

    #pragma unroll 2
    for (int e = e0; e < e1; e += 2) {
        int idx = e + half;
        bool valid = idx < e1;
        int   c = valid ? cols[idx] : c_fallback;  // 2-way load per warp
        float p = valid ? g_p[idx] : 0.f;

        uint4 vv = *(const uint4*)(g_v + (size_t)c * DD + l16 * 8);
        float2 v0 = __half22float2(*(__half2*)&vv.x);
        float2 v1 = __half22float2(*(__half2*)&vv.y);
        float2 v2 = __half22float2(*(__half2*)&vv.z);
        float2 v3 = __half22float2(*(__half2*)&vv.w);

        d += p;
        a0 = fmaf(p, v0.x, a0);
        a1 = fmaf(p, v0.y, a1);
        a2 = fmaf(p, v1.x, a2);
        a3 = fmaf(p, v1.y, a3);
        a4 = fmaf(p, v2.x, a4);
        a5 = fmaf(p, v2.y, a5);
        a6 = fmaf(p, v3.x, a6);
        a7 = fmaf(p, v3.y, a7);
    }

    // merge the two half-warps (lane l and l^16 hold the same dim group)
    d  += __shfl_xor_sync(0xFFFFFFFFu, d,  16);
    a0 += __shfl_xor_sync(0xFFFFFFFFu, a0, 16);
    a1 += __shfl_xor_sync(0xFFFFFFFFu, a1, 16);
    a2 += __shfl_xor_sync(0xFFFFFFFFu, a2, 16);
    a3 += __shfl_xor_sync(0xFFFFFFFFu, a3, 16);
    a4 += __shfl_xor_sync(0xFFFFFFFFu, a4, 16);
    a5 += __shfl_xor_sync(0xFFFFFFFFu, a5, 16);
    a6 += __shfl_xor_sync(0xFFFFFFFFu, a6, 16);
    a7 += __shfl_xor_sync(0xFFFFFFFFu, a7, 16);

    if (half == 0) {
        float inv = 1.f / d;
        float4 o0 = {a0 * inv, a1 * inv, a2 * inv, a3 * inv};
        float4 o1 = {a4 * inv, a5 * inv, a6 * inv, a7 * inv};
        ((float4*)orow)[l16 * 2]     = o0;
        ((float4*)orow)[l16 * 2 + 1] = o1;
    }
}

extern "C" void kernel_launch(void* const* d_in, const int* in_sizes, int n_in,
                              void* d_out, int out_size) {
    const float* query  = (const float*)d_in[0];
    const float* memory = (const float*)d_in[1];
    const float* adj    = (const float*)d_in[2];
    const float* Wq     = (const float*)d_in[3];
    const float* bq     = (const float*)d_in[4];
    const float* Wk     = (const float*)d_in[5];
    const float* bk     = (const float*)d_in[6];
    const float* Wv     = (const float*)d_in[7];
    const float* bv     = (const float*)d_in[8];
    const int*   rows   = (const int*)d_in[9];
    const int*   cols   = (const int*)d_in[10];
    float* out = (float*)d_out;

    const int smem_bytes = 2 * 128 * SW * sizeof(__half);  // 69632
    cudaFuncSetAttribute(proj_mma_kernel,
                         cudaFuncAttributeMaxDynamicSharedMemorySize, smem_bytes);

    dim3 pgrid((NN + 127) / 128, 3);
    proj_mma_kernel<<<pgrid, 256, smem_bytes>>>(query, memory,
                                                Wq, bq, Wk, bk, Wv, bv);
    build_rowptr<<<(NN + 1 + 255) / 256, 256>>>(rows);
    // half-warp per edge: 16 threads/edge -> EE*16 threads total
    score_kernel<<<(EE * 16 + 255) / 256, 256>>>(rows, cols, adj);
    attn_row_kernel<<<(NN * 32 + 255) / 256, 256>>>(cols, out);
}

// round 17
// speedup vs baseline: 1.5350x; 1.5350x over previous
#include <cuda_runtime.h>
#include <cuda_fp16.h>
#include <math.h>

#define NN 50000
#define MM 50000
#define EE 1600000
#define DD 128
#define SW 136   // smem tile stride in halves (272B: ldmatrix-aligned, conflict-free)

// Scratch (allocation-free rule: __device__ globals)
__device__ __half g_qh[NN * DD];
__device__ __half g_k[MM * DD];
__device__ __half g_v[MM * DD];
__device__ int    g_rowptr[NN + 1];

__device__ __forceinline__ float gelu_fast(float x) {
    float u = x * fmaf(x * x, 0.0356774081f, 0.7978845608f);
    float th;
    asm("tanh.approx.f32 %0, %1;" : "=f"(th) : "f"(u));
    return 0.5f * x * (1.0f + th);
}

__device__ __forceinline__ void mma16816(float* c,
    unsigned a0, unsigned a1, unsigned a2, unsigned a3,
    unsigned b0, unsigned b1)
{
    asm volatile(
        "mma.sync.aligned.m16n8k16.row.col.f32.f16.f16.f32 "
        "{%0,%1,%2,%3}, {%4,%5,%6,%7}, {%8,%9}, {%0,%1,%2,%3};\n"
        : "+f"(c[0]), "+f"(c[1]), "+f"(c[2]), "+f"(c[3])
        : "r"(a0), "r"(a1), "r"(a2), "r"(a3), "r"(b0), "r"(b1));
}

// ---------------------------------------------------------------------------
// Tensor-core projection: Y = gelu(X @ W + b), fp16 HMMA, fp32 accum.
// (unchanged — measured stable; ldmatrix A/B, coalesced epilogue)
// ---------------------------------------------------------------------------
__global__ __launch_bounds__(256, 2) void proj_mma_kernel(
    const float* __restrict__ query, const float* __restrict__ memory,
    const float* __restrict__ Wq, const float* __restrict__ bq,
    const float* __restrict__ Wk, const float* __restrict__ bk,
    const float* __restrict__ Wv, const float* __restrict__ bv)
{
    extern __shared__ __half smem[];
    __half* sW = smem;             // 128 x SW halves
    __half* sX = smem + 128 * SW;  // 128 x SW halves (reused for output)

    const float* X; const float* W; const float* b; __half* Y;
    if (blockIdx.y == 0)      { X = query;  W = Wq; b = bq; Y = g_qh; }
    else if (blockIdx.y == 1) { X = memory; W = Wk; b = bk; Y = g_k; }
    else                      { X = memory; W = Wv; b = bv; Y = g_v; }
    const int R = NN;

    const int t = threadIdx.x;
    const int row_base = blockIdx.x * 128;

    {
        const float2* W2 = (const float2*)W;
        const float2* X2 = (const float2*)X;
        #pragma unroll
        for (int i = t; i < 8192; i += 256) {
            int row = i >> 6;
            int col = (i & 63) * 2;
            float2 wv = W2[i];
            *(__half2*)(sW + row * SW + col) = __floats2half2_rn(wv.x, wv.y);
            int xr = row_base + row;
            if (xr > R - 1) xr = R - 1;
            float2 xv = X2[(size_t)xr * 64 + (i & 63)];
            *(__half2*)(sX + row * SW + col) = __floats2half2_rn(xv.x, xv.y);
        }
    }
    __syncthreads();

    const int w = t >> 5;
    const int lane = t & 31;
    const int g = lane >> 2;
    const int tg = lane & 3;
    const int mloc = w * 16;

    float acc[16][4];
    #pragma unroll
    for (int i = 0; i < 16; i++) {
        acc[i][0] = 0.f; acc[i][1] = 0.f; acc[i][2] = 0.f; acc[i][3] = 0.f;
    }

    const int a_row = mloc + (lane & 15);
    const int a_koff = (lane >> 4) << 3;
    const int lrow = lane & 15;
    const int lcoff = (lane >> 4) << 3;

    #pragma unroll
    for (int ks = 0; ks < 8; ks++) {
        unsigned a0, a1, a2, a3;
        unsigned abase = (unsigned)__cvta_generic_to_shared(
            sX + a_row * SW + ks * 16 + a_koff);
        asm volatile(
            "ldmatrix.sync.aligned.m8n8.x4.shared.b16 {%0,%1,%2,%3}, [%4];\n"
            : "=r"(a0), "=r"(a1), "=r"(a2), "=r"(a3) : "r"(abase));

        unsigned bbase = (unsigned)__cvta_generic_to_shared(
            sW + (ks * 16 + lrow) * SW + lcoff);
        #pragma unroll
        for (int nt = 0; nt < 16; nt += 2) {
            unsigned b0, b1, b2, b3;
            asm volatile(
                "ldmatrix.sync.aligned.m8n8.x4.trans.shared.b16 "
                "{%0,%1,%2,%3}, [%4];\n"
                : "=r"(b0), "=r"(b1), "=r"(b2), "=r"(b3)
                : "r"(bbase + (unsigned)(nt * 8 * 2)));
            mma16816(acc[nt],     a0, a1, a2, a3, b0, b1);
            mma16816(acc[nt + 1], a0, a1, a2, a3, b2, b3);
        }
    }

    __syncthreads();
    #pragma unroll
    for (int nt = 0; nt < 16; nt++) {
        int col = nt * 8 + 2 * tg;
        float2 bias = *(const float2*)(b + col);
        float o0 = gelu_fast(acc[nt][0] + bias.x);
        float o1 = gelu_fast(acc[nt][1] + bias.y);
        float o2 = gelu_fast(acc[nt][2] + bias.x);
        float o3 = gelu_fast(acc[nt][3] + bias.y);
        *(__half2*)(sX + (mloc + g) * SW + col)     = __floats2half2_rn(o0, o1);
        *(__half2*)(sX + (mloc + 8 + g) * SW + col) = __floats2half2_rn(o2, o3);
    }
    __syncthreads();

    {
        const int lr = t >> 4;
        const int c16 = t & 15;
        #pragma unroll
        for (int it = 0; it < 8; it++) {
            int row_local = it * 16 + lr;
            int row = row_base + row_local;
            if (row < R) {
                uint4 val = *(const uint4*)(sX + row_local * SW + c16 * 8);
                *(uint4*)(Y + (size_t)row * DD + c16 * 8) = val;
            }
        }
    }
}

// ---------------------------------------------------------------------------
// CSR row pointers from sorted rows[] via lower_bound.
// ---------------------------------------------------------------------------
__global__ void build_rowptr(const int* __restrict__ rows) {
    int i = blockIdx.x * blockDim.x + threadIdx.x;
    if (i > NN) return;
    int lo = 0, hi = EE;
    while (lo < hi) {
        int mid = (lo + hi) >> 1;
        if (rows[mid] < i) lo = mid + 1; else hi = mid;
    }
    g_rowptr[i] = lo;
}

// ---------------------------------------------------------------------------
// FUSED edge phase: warp per row, 2 edges per iteration.
// q fragment loaded ONCE per row (uint4/lane). Per iteration, half-warp h
// owns edge e+h: loads k-row + v-row uint4 (16 lanes x 16B = full 256B row,
// 2 wavefronts each), dots q.k via 5 HFMA2, butterfly-reduces within its
// 16-lane group (4 shfl; both halves reduce in parallel), computes
// p = exp2(s * adj * scale * log2e) on all lanes, accumulates d += p,
// a += p*v. No max subtraction (gelu-bounded scores, verified safe).
// Final cross-half merge + normalize once per row.
// ---------------------------------------------------------------------------
__global__ __launch_bounds__(256) void attn_fused_kernel(
    const int* __restrict__ cols, const float* __restrict__ adj,
    float* __restrict__ out)
{
    int row = (blockIdx.x * blockDim.x + threadIdx.x) >> 5;
    int lane = threadIdx.x & 31;
    if (row >= NN) return;

    int e0 = g_rowptr[row];
    int e1 = g_rowptr[row + 1];

    float* orow = out + (size_t)row * DD;
    const int half = lane >> 4;       // 0 or 1: which edge of the pair
    const int l16 = lane & 15;        // dim group: 8 dims starting at l16*8

    if (e0 == e1) {
        if (half == 0) {
            float4 z = {0.f, 0.f, 0.f, 0.f};
            ((float4*)orow)[l16 * 2]     = z;
            ((float4*)orow)[l16 * 2 + 1] = z;
        }
        return;
    }

    // q fragment: 8 halves (this lane's dim group), same for both halves
    uint4 qf = *(const uint4*)(g_qh + (size_t)row * DD + l16 * 8);
    const __half2 q0 = *(__half2*)&qf.x;
    const __half2 q1 = *(__half2*)&qf.y;
    const __half2 q2 = *(__half2*)&qf.z;
    const __half2 q3 = *(__half2*)&qf.w;

    const int c_fallback = cols[e0];
    const float SCALE_L2E = 0.1275611217f;   // (1/sqrt(128)) * log2(e)

    float d = 0.f;
    float a0 = 0.f, a1 = 0.f, a2 = 0.f, a3 = 0.f;
    float a4 = 0.f, a5 = 0.f, a6 = 0.f, a7 = 0.f;

    #pragma unroll 2
    for (int e = e0; e < e1; e += 2) {
        int idx = e + half;
        bool valid = idx < e1;
        int   c  = valid ? cols[idx] : c_fallback;
        float av = valid ? adj[idx] : 0.f;

        const __half* kr = g_k + (size_t)c * DD + l16 * 8;
        const __half* vr = g_v + (size_t)c * DD + l16 * 8;
        uint4 kk = *(const uint4*)kr;
        uint4 vv = *(const uint4*)vr;

        // dot(q, k) over this lane's 8 dims (fp16 chain depth 4)
        __half2 ac = __hmul2(q0, *(__half2*)&kk.x);
        ac = __hfma2(q1, *(__half2*)&kk.y, ac);
        ac = __hfma2(q2, *(__half2*)&kk.z, ac);
        ac = __hfma2(q3, *(__half2*)&kk.w, ac);
        float2 f = __half22float2(ac);
        float s = f.x + f.y;

        // reduce within 16-lane group (both halves in parallel)
        s += __shfl_xor_sync(0xFFFFFFFFu, s, 1);
        s += __shfl_xor_sync(0xFFFFFFFFu, s, 2);
        s += __shfl_xor_sync(0xFFFFFFFFu, s, 4);
        s += __shfl_xor_sync(0xFFFFFFFFu, s, 8);

        float p = valid ? exp2f(s * av * SCALE_L2E) : 0.f;

        float2 v0 = __half22float2(*(__half2*)&vv.x);
        float2 v1 = __half22float2(*(__half2*)&vv.y);
        float2 v2 = __half22float2(*(__half2*)&vv.z);
        float2 v3 = __half22float2(*(__half2*)&vv.w);

        d += p;
        a0 = fmaf(p, v0.x, a0);
        a1 = fmaf(p, v0.y, a1);
        a2 = fmaf(p, v1.x, a2);
        a3 = fmaf(p, v1.y, a3);
        a4 = fmaf(p, v2.x, a4);
        a5 = fmaf(p, v2.y, a5);
        a6 = fmaf(p, v3.x, a6);
        a7 = fmaf(p, v3.y, a7);
    }

    // merge the two half-warps (lane l and l^16 hold the same dim group)
    d  += __shfl_xor_sync(0xFFFFFFFFu, d,  16);
    a0 += __shfl_xor_sync(0xFFFFFFFFu, a0, 16);
    a1 += __shfl_xor_sync(0xFFFFFFFFu, a1, 16);
    a2 += __shfl_xor_sync(0xFFFFFFFFu, a2, 16);
    a3 += __shfl_xor_sync(0xFFFFFFFFu, a3, 16);
    a4 += __shfl_xor_sync(0xFFFFFFFFu, a4, 16);
    a5 += __shfl_xor_sync(0xFFFFFFFFu, a5, 16);
    a6 += __shfl_xor_sync(0xFFFFFFFFu, a6, 16);
    a7 += __shfl_xor_sync(0xFFFFFFFFu, a7, 16);

    if (half == 0) {
        float inv = 1.f / d;
        float4 o0 = {a0 * inv, a1 * inv, a2 * inv, a3 * inv};
        float4 o1 = {a4 * inv, a5 * inv, a6 * inv, a7 * inv};
        ((float4*)orow)[l16 * 2]     = o0;
        ((float4*)orow)[l16 * 2 + 1] = o1;
    }
}

extern "C" void kernel_launch(void* const* d_in, const int* in_sizes, int n_in,
                              void* d_out, int out_size) {
    const float* query  = (const float*)d_in[0];
    const float* memory = (const float*)d_in[1];
    const float* adj    = (const float*)d_in[2];
    const float* Wq     = (const float*)d_in[3];
    const float* bq     = (const float*)d_in[4];
    const float* Wk     = (const float*)d_in[5];
    const float* bk     = (const float*)d_in[6];
    const float* Wv     = (const float*)d_in[7];
    const float* bv     = (const float*)d_in[8];
    const int*   rows   = (const int*)d_in[9];
    const int*   cols   = (const int*)d_in[10];
    float* out = (float*)d_out;

    const int smem_bytes = 2 * 128 * SW * sizeof(__half);  // 69632
    cudaFuncSetAttribute(proj_mma_kernel,
                         cudaFuncAttributeMaxDynamicSharedMemorySize, smem_bytes);

    dim3 pgrid((NN + 127) / 128, 3);
    proj_mma_kernel<<<pgrid, 256, smem_bytes>>>(query, memory,
                                                Wq, bq, Wk, bk, Wv, bv);
    build_rowptr<<<(NN + 1 + 255) / 256, 256>>>(rows);
    attn_fused_kernel<<<(NN * 32 + 255) / 256, 256>>>(cols, adj, out);
}